// round 1
// baseline (speedup 1.0000x reference)
#include <cuda_runtime.h>
#include <math.h>

#define BB 2
#define CC 256
#define NN 4096
#define KKEEP 409   // int(0.1 * 4096)

// Scratch in device globals (no runtime allocation allowed).
__device__ float g_q[(size_t)BB*NN*CC];
__device__ float g_k[(size_t)BB*NN*CC];
__device__ float g_v[(size_t)BB*NN*CC];
__device__ float g_s[(size_t)BB*NN*NN];   // 134 MB score matrix

// ---------------------------------------------------------------------------
// Kernel 1: fused Q/K/V projection.  out[b][n][o] = sum_c x[b][c][n]*W[o][c] + bias[o]
// Tiles: 64(n) x 64(o) x 32(c), 256 threads, 4x4 per thread.
// ---------------------------------------------------------------------------
__global__ __launch_bounds__(256) void proj_kernel(
    const float* __restrict__ x,
    const float* __restrict__ Wq, const float* __restrict__ bq,
    const float* __restrict__ Wk, const float* __restrict__ bk,
    const float* __restrict__ Wv, const float* __restrict__ bv)
{
    const int p = blockIdx.z % 3;
    const int b = blockIdx.z / 3;
    const float* W; const float* bias; float* out;
    if (p == 0)      { W = Wq; bias = bq; out = g_q; }
    else if (p == 1) { W = Wk; bias = bk; out = g_k; }
    else             { W = Wv; bias = bv; out = g_v; }
    out += (size_t)b * NN * CC;
    const float* xb = x + (size_t)b * CC * NN;

    __shared__ float As[32][64];   // [c][n]
    __shared__ float Bs[32][65];   // [c][o]  (+1 pad for transposed stores)

    const int n0 = blockIdx.x * 64;
    const int o0 = blockIdx.y * 64;
    const int t  = threadIdx.x;
    const int tx = t & 15, ty = t >> 4;

    float acc[4][4] = {};
    for (int k0 = 0; k0 < CC; k0 += 32) {
        #pragma unroll
        for (int i = 0; i < 2; i++) {          // A: 32c x 64n = 512 float4
            int idx = t + i*256;
            int cc = idx >> 4, f4 = idx & 15;
            float4 v4 = *(const float4*)(xb + (size_t)(k0+cc)*NN + n0 + f4*4);
            *(float4*)&As[cc][f4*4] = v4;
        }
        #pragma unroll
        for (int i = 0; i < 2; i++) {          // B: 64o x 32c = 512 float4
            int idx = t + i*256;
            int oo = idx >> 3, f4 = idx & 7;
            float4 v4 = *(const float4*)(W + (size_t)(o0+oo)*CC + k0 + f4*4);
            Bs[f4*4+0][oo] = v4.x; Bs[f4*4+1][oo] = v4.y;
            Bs[f4*4+2][oo] = v4.z; Bs[f4*4+3][oo] = v4.w;
        }
        __syncthreads();
        #pragma unroll
        for (int kk = 0; kk < 32; kk++) {
            float a[4], bv2[4];
            #pragma unroll
            for (int i = 0; i < 4; i++) a[i]   = As[kk][ty*4+i];
            #pragma unroll
            for (int j = 0; j < 4; j++) bv2[j] = Bs[kk][tx*4+j];
            #pragma unroll
            for (int i = 0; i < 4; i++)
                #pragma unroll
                for (int j = 0; j < 4; j++)
                    acc[i][j] += a[i] * bv2[j];
        }
        __syncthreads();
    }
    #pragma unroll
    for (int i = 0; i < 4; i++) {
        int n = n0 + ty*4 + i;
        #pragma unroll
        for (int j = 0; j < 4; j++) {
            int o = o0 + tx*4 + j;
            out[(size_t)n*CC + o] = acc[i][j] + bias[o];
        }
    }
}

// ---------------------------------------------------------------------------
// Kernel 2: S = Q * K^T / 16.  128x128x16 tiles, 256 threads, 8x8 per thread.
// ---------------------------------------------------------------------------
__global__ __launch_bounds__(256) void scores_kernel()
{
    const int b = blockIdx.z;
    const float* Q = g_q + (size_t)b*NN*CC;
    const float* K = g_k + (size_t)b*NN*CC;
    float* S = g_s + (size_t)b*NN*NN;

    const int n0 = blockIdx.y * 128;
    const int m0 = blockIdx.x * 128;

    __shared__ float As[16][128];  // [c][n]
    __shared__ float Bs[16][128];  // [c][m]

    const int t  = threadIdx.x;
    const int tx = t & 15, ty = t >> 4;

    float acc[8][8] = {};
    for (int k0 = 0; k0 < CC; k0 += 16) {
        #pragma unroll
        for (int i = 0; i < 2; i++) {   // 128 rows x 16 c = 512 float4 each matrix
            int idx = t + i*256;
            int row = idx >> 2, f4 = idx & 3;
            float4 va = *(const float4*)(Q + (size_t)(n0+row)*CC + k0 + f4*4);
            As[f4*4+0][row]=va.x; As[f4*4+1][row]=va.y;
            As[f4*4+2][row]=va.z; As[f4*4+3][row]=va.w;
            float4 vb = *(const float4*)(K + (size_t)(m0+row)*CC + k0 + f4*4);
            Bs[f4*4+0][row]=vb.x; Bs[f4*4+1][row]=vb.y;
            Bs[f4*4+2][row]=vb.z; Bs[f4*4+3][row]=vb.w;
        }
        __syncthreads();
        #pragma unroll
        for (int kk = 0; kk < 16; kk++) {
            float a[8], bb[8];
            *(float4*)&a[0]  = *(const float4*)&As[kk][ty*8];
            *(float4*)&a[4]  = *(const float4*)&As[kk][ty*8+4];
            *(float4*)&bb[0] = *(const float4*)&Bs[kk][tx*8];
            *(float4*)&bb[4] = *(const float4*)&Bs[kk][tx*8+4];
            #pragma unroll
            for (int i = 0; i < 8; i++)
                #pragma unroll
                for (int j = 0; j < 8; j++)
                    acc[i][j] += a[i] * bb[j];
        }
        __syncthreads();
    }
    const float scale = 0.0625f;   // 1/sqrt(256)
    #pragma unroll
    for (int i = 0; i < 8; i++) {
        size_t roff = (size_t)(n0 + ty*8 + i) * NN + m0 + tx*8;
        float4 v0 = make_float4(acc[i][0]*scale, acc[i][1]*scale, acc[i][2]*scale, acc[i][3]*scale);
        float4 v1 = make_float4(acc[i][4]*scale, acc[i][5]*scale, acc[i][6]*scale, acc[i][7]*scale);
        *(float4*)(S + roff)     = v0;
        *(float4*)(S + roff + 4) = v1;
    }
}

// ---------------------------------------------------------------------------
// Kernel 3: per-row exact top-409 (radix select on order-preserving keys),
// softmax over selected, sparse weighted sum with V. One block per (n, b).
// ---------------------------------------------------------------------------
__device__ __forceinline__ unsigned f2o(float f) {
    unsigned u = __float_as_uint(f);
    return u ^ ((unsigned)((int)u >> 31) | 0x80000000u);
}

__global__ __launch_bounds__(256) void topk_av_kernel(float* __restrict__ out)
{
    const int n = blockIdx.x;
    const int b = blockIdx.y;
    const int t = threadIdx.x;

    __shared__ float s_row[NN];         // 16 KB
    __shared__ int   hist[256];
    __shared__ int   eqc[256];
    __shared__ int   mlist[KKEEP + 32];
    __shared__ float wlist[KKEEP + 32];
    __shared__ float red[256];
    __shared__ unsigned sh_prefix;
    __shared__ int sh_krem, sh_cnt;
    __shared__ float sh_max;

    const float* Srow = g_s + ((size_t)b*NN + n)*NN;

    float lmax = -INFINITY;
    for (int i = t; i < NN; i += 256) {
        float v = Srow[i];
        s_row[i] = v;
        lmax = fmaxf(lmax, v);
    }
    red[t] = lmax; __syncthreads();
    for (int s = 128; s > 0; s >>= 1) {
        if (t < s) red[t] = fmaxf(red[t], red[t+s]);
        __syncthreads();
    }
    if (t == 0) { sh_max = red[0]; sh_krem = KKEEP; sh_prefix = 0u; sh_cnt = 0; }
    __syncthreads();

    // Exact radix select: find the KKEEP-th largest key (4 x 8-bit passes, MSB first)
    for (int shift = 24; shift >= 0; shift -= 8) {
        hist[t] = 0; __syncthreads();
        unsigned pref = sh_prefix;
        for (int i = t; i < NN; i += 256) {
            unsigned u = f2o(s_row[i]);
            bool match = (shift == 24) || ((u >> (shift + 8)) == pref);
            if (match) atomicAdd(&hist[(u >> shift) & 255u], 1);
        }
        __syncthreads();
        if (t == 0) {
            int krem = sh_krem, cum = 0, d;
            for (d = 255; d >= 0; d--) {
                int c2 = hist[d];
                if (cum + c2 >= krem) break;
                cum += c2;
            }
            sh_krem = krem - cum;
            sh_prefix = (sh_prefix << 8) | (unsigned)d;
        }
        __syncthreads();
    }
    const unsigned uT  = sh_prefix;   // key of the k-th largest element
    const int       r  = sh_krem;     // # elements equal to uT to include (lowest idx first)
    const float   smax = sh_max;

    // Count equals per blocked chunk [t*16, t*16+16) for index-ordered tie capping
    int cnteq = 0;
    {
        int base = t * 16;
        #pragma unroll
        for (int i = 0; i < 16; i++)
            if (f2o(s_row[base + i]) == uT) cnteq++;
    }
    eqc[t] = cnteq; __syncthreads();
    for (int off = 1; off < 256; off <<= 1) {     // inclusive scan
        int v = (t >= off) ? eqc[t - off] : 0;
        __syncthreads();
        eqc[t] += v;
        __syncthreads();
    }
    const int eqExcl = eqc[t] - cnteq;

    // Build (index, weight) list of exactly KKEEP selected elements
    {
        int base = t * 16;
        int local = 0;
        #pragma unroll
        for (int i = 0; i < 16; i++) {
            float s = s_row[base + i];
            unsigned u = f2o(s);
            bool sel = false;
            if (u > uT) sel = true;
            else if (u == uT) { if (eqExcl + local < r) sel = true; local++; }
            if (sel) {
                int pos = atomicAdd(&sh_cnt, 1);
                mlist[pos] = base + i;
                wlist[pos] = __expf(s - smax);
            }
        }
    }
    __syncthreads();
    const int cnt = sh_cnt;           // == KKEEP

    // Z = sum of selected weights
    float z = 0.f;
    for (int i = t; i < cnt; i += 256) z += wlist[i];
    red[t] = z; __syncthreads();
    for (int s = 128; s > 0; s >>= 1) {
        if (t < s) red[t] += red[t+s];
        __syncthreads();
    }
    const float invZ = 1.0f / red[0];

    // Sparse AV: thread t owns channel c = t.  V is L2-resident (8 MB total).
    const float* Vb = g_v + (size_t)b*NN*CC;
    float acc = 0.f;
    int i = 0;
    for (; i + 4 <= cnt; i += 4) {
        float w0 = wlist[i],   w1 = wlist[i+1], w2 = wlist[i+2], w3 = wlist[i+3];
        int   m0 = mlist[i],   m1 = mlist[i+1], m2 = mlist[i+2], m3 = mlist[i+3];
        acc += w0 * Vb[(size_t)m0*CC + t];
        acc += w1 * Vb[(size_t)m1*CC + t];
        acc += w2 * Vb[(size_t)m2*CC + t];
        acc += w3 * Vb[(size_t)m3*CC + t];
    }
    for (; i < cnt; i++) acc += wlist[i] * Vb[(size_t)mlist[i]*CC + t];

    // output layout [B, C, H, W]: out[b][c][n]
    out[((size_t)b*CC + t)*NN + n] = acc * invZ;
}

// ---------------------------------------------------------------------------
extern "C" void kernel_launch(void* const* d_in, const int* in_sizes, int n_in,
                              void* d_out, int out_size)
{
    const float* x  = (const float*)d_in[0];
    const float* Wq = (const float*)d_in[1];
    const float* bq = (const float*)d_in[2];
    const float* Wk = (const float*)d_in[3];
    const float* bk = (const float*)d_in[4];
    const float* Wv = (const float*)d_in[5];
    const float* bv = (const float*)d_in[6];
    float* out = (float*)d_out;

    proj_kernel  <<<dim3(NN/64,  CC/64, BB*3), 256>>>(x, Wq, bq, Wk, bk, Wv, bv);
    scores_kernel<<<dim3(NN/128, NN/128, BB),  256>>>();
    topk_av_kernel<<<dim3(NN, BB), 256>>>(out);
}

// round 4
// speedup vs baseline: 1.1159x; 1.1159x over previous
#include <cuda_runtime.h>
#include <cuda_fp16.h>
#include <math.h>
#include <stdint.h>

#define BB 2
#define CC 256
#define NN 4096
#define KKEEP 409   // int(0.1 * 4096)

// Scratch in device globals (no runtime allocation allowed).
__device__ float  g_q[(size_t)BB*NN*CC];          // Q [b][n][c] fp32
__device__ float  g_k[(size_t)BB*NN*CC];          // K [b][n][c] fp32
__device__ __half2 g_vh[(size_t)BB*NN*(CC/2)];    // V [b][n][c/2] fp16x2
__device__ float  g_s[(size_t)BB*NN*NN];          // 134 MB score matrix

// ---------------------------------------------------------------------------
// Kernel 1: fused Q/K/V projection.  q/k fp32 [n][c], v fp16x2 [n][c/2]
// ---------------------------------------------------------------------------
__global__ __launch_bounds__(256) void proj_kernel(
    const float* __restrict__ x,
    const float* __restrict__ Wq, const float* __restrict__ bq,
    const float* __restrict__ Wk, const float* __restrict__ bk,
    const float* __restrict__ Wv, const float* __restrict__ bv)
{
    const int p = blockIdx.z % 3;
    const int b = blockIdx.z / 3;
    const float* W; const float* bias;
    if (p == 0)      { W = Wq; bias = bq; }
    else if (p == 1) { W = Wk; bias = bk; }
    else             { W = Wv; bias = bv; }
    const float* xb = x + (size_t)b * CC * NN;

    __shared__ float As[32][64];   // [c][n]
    __shared__ float Bs[32][65];   // [c][o]

    const int n0 = blockIdx.x * 64;
    const int o0 = blockIdx.y * 64;
    const int t  = threadIdx.x;
    const int tx = t & 15, ty = t >> 4;   // tx -> o, ty -> n

    float acc[4][4] = {};   // [n][o]
    for (int k0 = 0; k0 < CC; k0 += 32) {
        #pragma unroll
        for (int i = 0; i < 2; i++) {
            int idx = t + i*256;
            int cc = idx >> 4, f4 = idx & 15;
            float4 v4 = *(const float4*)(xb + (size_t)(k0+cc)*NN + n0 + f4*4);
            *(float4*)&As[cc][f4*4] = v4;
        }
        #pragma unroll
        for (int i = 0; i < 2; i++) {
            int idx = t + i*256;
            int oo = idx >> 3, f4 = idx & 7;
            float4 v4 = *(const float4*)(W + (size_t)(o0+oo)*CC + k0 + f4*4);
            Bs[f4*4+0][oo] = v4.x; Bs[f4*4+1][oo] = v4.y;
            Bs[f4*4+2][oo] = v4.z; Bs[f4*4+3][oo] = v4.w;
        }
        __syncthreads();
        #pragma unroll
        for (int kk = 0; kk < 32; kk++) {
            float a[4], bv2[4];
            #pragma unroll
            for (int i = 0; i < 4; i++) a[i]   = As[kk][ty*4+i];
            #pragma unroll
            for (int j = 0; j < 4; j++) bv2[j] = Bs[kk][tx*4+j];
            #pragma unroll
            for (int i = 0; i < 4; i++)
                #pragma unroll
                for (int j = 0; j < 4; j++)
                    acc[i][j] += a[i] * bv2[j];
        }
        __syncthreads();
    }
    if (p < 2) {
        float* out = (p == 0 ? g_q : g_k) + (size_t)b * NN * CC;
        #pragma unroll
        for (int i = 0; i < 4; i++) {
            int n = n0 + ty*4 + i;
            #pragma unroll
            for (int j = 0; j < 4; j++) {
                int o = o0 + tx*4 + j;
                out[(size_t)n*CC + o] = acc[i][j] + bias[o];
            }
        }
    } else {
        __half2* outv = g_vh + (size_t)b * NN * (CC/2);
        float b0 = bias[o0+tx*4+0], b1 = bias[o0+tx*4+1];
        float b2 = bias[o0+tx*4+2], b3 = bias[o0+tx*4+3];
        #pragma unroll
        for (int i = 0; i < 4; i++) {
            int n = n0 + ty*4 + i;
            size_t base = (size_t)n*(CC/2) + (o0 + tx*4)/2;
            outv[base]     = __floats2half2_rn(acc[i][0]+b0, acc[i][1]+b1);
            outv[base + 1] = __floats2half2_rn(acc[i][2]+b2, acc[i][3]+b3);
        }
    }
}

// ---------------------------------------------------------------------------
// Kernel 2: S = Q * K^T / 16 via mma.sync tf32 (m16n8k8), 3xTF32 compensated:
//   A*B ~= Ab*Bb + Ab*Bs + As*Bb   (big = tf32(x), small = tf32(x - big))
// CTA tile 128(i) x 128(j), 8 warps (32i x 64j each), K in 8 steps of 32.
// Register-staged double-buffered smem pipeline, 1 syncthreads per step.
// ---------------------------------------------------------------------------
__device__ __forceinline__ uint32_t f2tf(float f) {
    uint32_t u;
    asm("cvt.rna.tf32.f32 %0, %1;" : "=r"(u) : "f"(f));
    return u;
}

// smem word layout per matrix: kc*1032 + row*8 + c2*2   (pair (c2, c2+4) as uint2)
#define SC_MAT  4128            // words per matrix buffer
#define SC_BUF  (4*SC_MAT)      // A_big, A_small, B_big, B_small
#define SC_SMEM_BYTES (2*SC_BUF*4)   // 132096 bytes

__device__ __forceinline__ void mma_tf32(float* c, const uint32_t* a, uint32_t b0, uint32_t b1) {
    asm volatile(
        "mma.sync.aligned.m16n8k8.row.col.f32.tf32.tf32.f32 "
        "{%0,%1,%2,%3}, {%4,%5,%6,%7}, {%8,%9}, {%0,%1,%2,%3};"
        : "+f"(c[0]), "+f"(c[1]), "+f"(c[2]), "+f"(c[3])
        : "r"(a[0]), "r"(a[1]), "r"(a[2]), "r"(a[3]), "r"(b0), "r"(b1));
}

__global__ __launch_bounds__(256) void scores_mma_kernel()
{
    extern __shared__ uint32_t smw[];
    const int t    = threadIdx.x;
    const int lane = t & 31;
    const int wid  = t >> 5;
    const int b  = blockIdx.z;
    const int m0 = blockIdx.x * 128;   // j: K rows
    const int n0 = blockIdx.y * 128;   // i: Q rows
    const float* Q = g_q + (size_t)b*NN*CC;
    const float* K = g_k + (size_t)b*NN*CC;

    const int r  = lane >> 2;          // 0..7
    const int c2 = lane & 3;           // 0..3
    const int ib = (wid >> 1) * 32;    // warp i-offset
    const int jb = (wid & 1) * 64;     // warp j-offset

    // per-thread load tasks: tau = t + p*256 -> row = tau>>2, kc = tau&3
    const int row0 = t >> 2,         kc0 = t & 3;
    const int row1 = (t + 256) >> 2, kc1 = t & 3;

    float4 qa[2][2], ka[2][2];

    #define SC_LOAD(k0)  do { \
        const float4* q0p = (const float4*)(Q + (size_t)(n0+row0)*CC + (k0) + kc0*8); \
        qa[0][0] = q0p[0]; qa[0][1] = q0p[1]; \
        const float4* k0p = (const float4*)(K + (size_t)(m0+row0)*CC + (k0) + kc0*8); \
        ka[0][0] = k0p[0]; ka[0][1] = k0p[1]; \
        const float4* q1p = (const float4*)(Q + (size_t)(n0+row1)*CC + (k0) + kc1*8); \
        qa[1][0] = q1p[0]; qa[1][1] = q1p[1]; \
        const float4* k1p = (const float4*)(K + (size_t)(m0+row1)*CC + (k0) + kc1*8); \
        ka[1][0] = k1p[0]; ka[1][1] = k1p[1]; \
    } while (0)

    #define SPLIT(xv, bu, su) { (bu) = f2tf(xv); (su) = f2tf((xv) - __uint_as_float(bu)); }

    // writes big at dst, small at dst+SC_MAT
    #define SC_ST1(dst, lo, hi) do { \
        uint32_t B0,B1,B2,B3,B4,B5,B6,B7, S0,S1,S2,S3,S4,S5,S6,S7; \
        SPLIT((lo).x,B0,S0); SPLIT((hi).x,B1,S1); SPLIT((lo).y,B2,S2); SPLIT((hi).y,B3,S3); \
        SPLIT((lo).z,B4,S4); SPLIT((hi).z,B5,S5); SPLIT((lo).w,B6,S6); SPLIT((hi).w,B7,S7); \
        *(uint4*)(dst)              = make_uint4(B0,B1,B2,B3); \
        *(uint4*)((dst)+4)          = make_uint4(B4,B5,B6,B7); \
        *(uint4*)((dst)+SC_MAT)     = make_uint4(S0,S1,S2,S3); \
        *(uint4*)((dst)+SC_MAT+4)   = make_uint4(S4,S5,S6,S7); \
    } while (0)

    #define SC_STORE(buf) do { \
        uint32_t* base = smw + (buf)*SC_BUF; \
        uint32_t* d0 = base + kc0*1032 + row0*8; \
        SC_ST1(d0, qa[0][0], qa[0][1]); \
        SC_ST1(d0 + 2*SC_MAT, ka[0][0], ka[0][1]); \
        uint32_t* d1 = base + kc1*1032 + row1*8; \
        SC_ST1(d1, qa[1][0], qa[1][1]); \
        SC_ST1(d1 + 2*SC_MAT, ka[1][0], ka[1][1]); \
    } while (0)

    float acc[2][8][4];
    #pragma unroll
    for (int mt = 0; mt < 2; mt++)
        #pragma unroll
        for (int nt = 0; nt < 8; nt++)
            #pragma unroll
            for (int q = 0; q < 4; q++) acc[mt][nt][q] = 0.f;

    SC_LOAD(0);
    SC_STORE(0);

    for (int s = 0; s < 8; s++) {
        __syncthreads();
        if (s < 7) SC_LOAD((s+1)*32);

        const uint32_t* A  = smw + (s & 1)*SC_BUF;   // A_big; A_small at +SC_MAT
        const uint32_t* Bm = A + 2*SC_MAT;           // B_big; B_small at +SC_MAT
        #pragma unroll
        for (int kc = 0; kc < 4; kc++) {
            uint32_t afb[2][4], afs[2][4];
            #pragma unroll
            for (int mt = 0; mt < 2; mt++) {
                const uint32_t* pa = A + kc*1032 + (ib + mt*16 + r)*8 + c2*2;
                uint2 lo  = *(const uint2*)pa;
                uint2 hi  = *(const uint2*)(pa + 64);            // +8 rows
                uint2 los = *(const uint2*)(pa + SC_MAT);
                uint2 his = *(const uint2*)(pa + SC_MAT + 64);
                afb[mt][0] = lo.x;  afb[mt][1] = hi.x;  afb[mt][2] = lo.y;  afb[mt][3] = hi.y;
                afs[mt][0] = los.x; afs[mt][1] = his.x; afs[mt][2] = los.y; afs[mt][3] = his.y;
            }
            uint2 bfb[8], bfs[8];
            #pragma unroll
            for (int nt = 0; nt < 8; nt++) {
                const uint32_t* pb = Bm + kc*1032 + (jb + nt*8 + r)*8 + c2*2;
                bfb[nt] = *(const uint2*)pb;
                bfs[nt] = *(const uint2*)(pb + SC_MAT);
            }
            #pragma unroll
            for (int mt = 0; mt < 2; mt++)
                #pragma unroll
                for (int nt = 0; nt < 8; nt++) {
                    mma_tf32(acc[mt][nt], afs[mt], bfb[nt].x, bfb[nt].y);  // As*Bb
                    mma_tf32(acc[mt][nt], afb[mt], bfs[nt].x, bfs[nt].y);  // Ab*Bs
                    mma_tf32(acc[mt][nt], afb[mt], bfb[nt].x, bfb[nt].y);  // Ab*Bb
                }
        }
        if (s < 7) SC_STORE((s+1) & 1);
    }

    // Epilogue: scale + store.  c0:(r, 2c2) c1:(r, 2c2+1) c2:(r+8, 2c2) c3:(r+8, 2c2+1)
    float* S = g_s + (size_t)b*NN*NN;
    const float sc = 0.0625f;  // 1/sqrt(256)
    #pragma unroll
    for (int mt = 0; mt < 2; mt++) {
        #pragma unroll
        for (int nt = 0; nt < 8; nt++) {
            int rowi = n0 + ib + mt*16 + r;
            int colj = m0 + jb + nt*8 + 2*c2;
            float2 v0 = make_float2(acc[mt][nt][0]*sc, acc[mt][nt][1]*sc);
            float2 v1 = make_float2(acc[mt][nt][2]*sc, acc[mt][nt][3]*sc);
            *(float2*)(S + (size_t)rowi*NN + colj)     = v0;
            *(float2*)(S + (size_t)(rowi+8)*NN + colj) = v1;
        }
    }
}

// ---------------------------------------------------------------------------
// Kernel 3: per-row exact top-409 radix select + softmax + sparse AV (fp16 V).
// One block (256 threads) per (n, b).
// ---------------------------------------------------------------------------
__device__ __forceinline__ unsigned f2o(float f) {
    unsigned u = __float_as_uint(f);
    return u ^ ((unsigned)((int)u >> 31) | 0x80000000u);
}

__global__ __launch_bounds__(256) void topk_av_kernel(float* __restrict__ out)
{
    const int n = blockIdx.x;
    const int b = blockIdx.y;
    const int t = threadIdx.x;

    __shared__ float s_row[NN];         // 16 KB (reused as float2[128] later)
    __shared__ int   hist[256];
    __shared__ int   eqc[256];
    __shared__ int   mlist[KKEEP + 32];
    __shared__ float wlist[KKEEP + 32];
    __shared__ float red[256];
    __shared__ unsigned sh_prefix;
    __shared__ int sh_krem, sh_cnt;
    __shared__ float sh_max;

    const float* Srow = g_s + ((size_t)b*NN + n)*NN;

    float lmax = -INFINITY;
    for (int i = t; i < NN; i += 256) {
        float v = Srow[i];
        s_row[i] = v;
        lmax = fmaxf(lmax, v);
    }
    red[t] = lmax; __syncthreads();
    for (int s = 128; s > 0; s >>= 1) {
        if (t < s) red[t] = fmaxf(red[t], red[t+s]);
        __syncthreads();
    }
    if (t == 0) { sh_max = red[0]; sh_krem = KKEEP; sh_prefix = 0u; sh_cnt = 0; }
    __syncthreads();

    // Exact radix select: KKEEP-th largest key (4 x 8-bit passes, MSB first)
    for (int shift = 24; shift >= 0; shift -= 8) {
        hist[t] = 0; __syncthreads();
        unsigned pref = sh_prefix;
        for (int i = t; i < NN; i += 256) {
            unsigned u = f2o(s_row[i]);
            bool match = (shift == 24) || ((u >> (shift + 8)) == pref);
            if (match) atomicAdd(&hist[(u >> shift) & 255u], 1);
        }
        __syncthreads();
        if (t == 0) {
            int krem = sh_krem, cum = 0, d;
            for (d = 255; d >= 0; d--) {
                int c2 = hist[d];
                if (cum + c2 >= krem) break;
                cum += c2;
            }
            sh_krem = krem - cum;
            sh_prefix = (sh_prefix << 8) | (unsigned)d;
        }
        __syncthreads();
    }
    const unsigned uT  = sh_prefix;
    const int       rr = sh_krem;
    const float   smax = sh_max;

    // Count equals per blocked chunk [t*16, t*16+16) for index-ordered tie capping
    int cnteq = 0;
    {
        int base = t * 16;
        #pragma unroll
        for (int i = 0; i < 16; i++)
            if (f2o(s_row[base + i]) == uT) cnteq++;
    }
    eqc[t] = cnteq; __syncthreads();
    for (int off = 1; off < 256; off <<= 1) {
        int v = (t >= off) ? eqc[t - off] : 0;
        __syncthreads();
        eqc[t] += v;
        __syncthreads();
    }
    const int eqExcl = eqc[t] - cnteq;

    // Build (index, weight) list of exactly KKEEP selected elements
    {
        int base = t * 16;
        int local = 0;
        #pragma unroll
        for (int i = 0; i < 16; i++) {
            float s = s_row[base + i];
            unsigned u = f2o(s);
            bool sel = false;
            if (u > uT) sel = true;
            else if (u == uT) { if (eqExcl + local < rr) sel = true; local++; }
            if (sel) {
                int pos = atomicAdd(&sh_cnt, 1);
                mlist[pos] = base + i;
                wlist[pos] = __expf(s - smax);
            }
        }
    }
    __syncthreads();
    const int cnt = sh_cnt;           // == KKEEP

    // Z = sum of selected weights
    float z = 0.f;
    for (int i = t; i < cnt; i += 256) z += wlist[i];
    red[t] = z; __syncthreads();
    for (int s = 128; s > 0; s >>= 1) {
        if (t < s) red[t] += red[t+s];
        __syncthreads();
    }
    const float invZ = 1.0f / red[0];
    __syncthreads();   // s_row reuse below

    // Sparse AV: thread (half, c2) owns channel pair c2; halves split rows.
    const __half2* Vb = g_vh + (size_t)b*NN*(CC/2);
    const int c2   = t & 127;
    const int half = t >> 7;
    float accx = 0.f, accy = 0.f;
    int i = half;
    for (; i + 6 <= cnt; i += 8) {
        float w0 = wlist[i],   w1 = wlist[i+2], w2 = wlist[i+4], w3 = wlist[i+6];
        int   m0 = mlist[i],   m1 = mlist[i+2], m2 = mlist[i+4], m3 = mlist[i+6];
        float2 v0 = __half22float2(Vb[(size_t)m0*(CC/2) + c2]);
        float2 v1 = __half22float2(Vb[(size_t)m1*(CC/2) + c2]);
        float2 v2 = __half22float2(Vb[(size_t)m2*(CC/2) + c2]);
        float2 v3 = __half22float2(Vb[(size_t)m3*(CC/2) + c2]);
        accx += w0*v0.x + w1*v1.x + w2*v2.x + w3*v3.x;
        accy += w0*v0.y + w1*v1.y + w2*v2.y + w3*v3.y;
    }
    for (; i < cnt; i += 2) {
        float w = wlist[i];
        float2 v = __half22float2(Vb[(size_t)mlist[i]*(CC/2) + c2]);
        accx += w*v.x; accy += w*v.y;
    }

    // Combine the two halves via smem, then write out[b][c][n].
    float2* comb = (float2*)s_row;
    if (half == 1) comb[c2] = make_float2(accx, accy);
    __syncthreads();
    if (half == 0) {
        float2 o2 = comb[c2];
        accx += o2.x; accy += o2.y;
        out[((size_t)b*CC + 2*c2)    *NN + n] = accx * invZ;
        out[((size_t)b*CC + 2*c2 + 1)*NN + n] = accy * invZ;
    }
}

// ---------------------------------------------------------------------------
extern "C" void kernel_launch(void* const* d_in, const int* in_sizes, int n_in,
                              void* d_out, int out_size)
{
    const float* x  = (const float*)d_in[0];
    const float* Wq = (const float*)d_in[1];
    const float* bq = (const float*)d_in[2];
    const float* Wk = (const float*)d_in[3];
    const float* bk = (const float*)d_in[4];
    const float* Wv = (const float*)d_in[5];
    const float* bv = (const float*)d_in[6];
    float* out = (float*)d_out;

    cudaFuncSetAttribute(scores_mma_kernel,
                         cudaFuncAttributeMaxDynamicSharedMemorySize, SC_SMEM_BYTES);

    proj_kernel      <<<dim3(NN/64,  CC/64, BB*3), 256>>>(x, Wq, bq, Wk, bk, Wv, bv);
    scores_mma_kernel<<<dim3(NN/128, NN/128, BB),  256, SC_SMEM_BYTES>>>();
    topk_av_kernel   <<<dim3(NN, BB), 256>>>(out);
}